// round 5
// baseline (speedup 1.0000x reference)
#include <cuda_runtime.h>

#define DD 64
#define H_ 256
#define W_ 512
#define HW_ (H_ * W_)
#define B_ 8
#define NPIX (B_ * HW_)
#define VEC 2
#define TPB 128
#define NTHREADS (NPIX / VEC)          // 524288
#define NBLOCKS (NTHREADS / TPB)       // 4096
#define PF 8                            // prefetch depth (planes)

__device__ double g_part[NBLOCKS];
__device__ unsigned int g_pcnt[NBLOCKS];
__device__ unsigned int g_ticket;      // zero-init at load; last block resets each launch

__global__ __launch_bounds__(TPB, 10) void sce_main(const float* __restrict__ sim,
                                                    const float* __restrict__ gt,
                                                    float* __restrict__ out) {
    int t = blockIdx.x * TPB + threadIdx.x;
    long long base = (long long)t * VEC;
    int b = (int)(base / HW_);
    int hw = (int)(base - (long long)b * HW_);

    float2 g2 = *reinterpret_cast<const float2*>(gt + base);
    float gts[VEC] = {g2.x, g2.y};

    const float E1  = 2.718281828459045f;    // e
    const float IE1 = 0.3678794411714423f;   // 1/e
    const float C1  = 0.15651764274966565f;  // 1/(e^2-1)
    const float C2  = 1.1565176427496657f;   // 1/(1-e^-2)

    // u_d = e^{(2d-gt)/2}, v_d = e^{(gt-2d)/2}; p_d = min(u,v)^2. |gt/2|<=63: in range.
    float u[VEC], v[VEC], esum[VEC], pts[VEC];
#pragma unroll
    for (int j = 0; j < VEC; ++j) {
        float hg = 0.5f * gts[j];
        u[j] = __expf(-hg);
        v[j] = __expf(hg);
        esum[j] = 0.f; pts[j] = 0.f;
    }

    const float* sbase = sim + (long long)b * DD * HW_ + hw;

    auto body = [&](float2 s2) {
        float sv[VEC] = {s2.x, s2.y};
#pragma unroll
        for (int j = 0; j < VEC; ++j) {
            float s = sv[j];
            esum[j] += __expf(s);
            float mm = fminf(u[j], v[j]);
            pts[j] = fmaf(mm * mm, s, pts[j]);
            u[j] *= E1;
            v[j] *= IE1;
        }
    };

    // Rotating 8-deep prefetch: ~8 LDG.64 in flight per warp at all times.
    float2 buf[PF];
    const float* p = sbase;
#pragma unroll
    for (int k = 0; k < PF; ++k)
        buf[k] = __ldcs(reinterpret_cast<const float2*>(p + (long long)k * HW_));

#pragma unroll 1
    for (int db = 0; db < DD - PF; db += PF) {
#pragma unroll
        for (int k = 0; k < PF; ++k) {
            float2 tmp = __ldcs(reinterpret_cast<const float2*>(p + (long long)(PF + k) * HW_));
            body(buf[k]);
            buf[k] = tmp;
        }
        p += (long long)PF * HW_;
    }
#pragma unroll
    for (int k = 0; k < PF; ++k) body(buf[k]);

    double lsum = 0.0;
    unsigned int lcnt = 0u;
#pragma unroll
    for (int j = 0; j < VEC; ++j) {
        if (isfinite(gts[j])) {
            // Closed-form sum of Laplace weights (two geometric series):
            // t = gt - 2*floor(gt/2); ptn = (e^{2-t}-e^{-gt})*C1 + (e^{t-2}-e^{gt-128})*C2
            float gtv = gts[j];
            float m0 = floorf(gtv * 0.5f);
            float tt = fmaf(-2.0f, m0, gtv);          // [0, 2)
            float et2 = __expf(tt - 2.0f);            // e^{t-2}
            float e2t = 1.0f / et2;                   // e^{2-t}
            float eng = __expf(-gtv);                 // e^{-gt}
            float wsq = __expf(gtv - 128.0f);         // e^{gt-128}
            float ptn = (e2t - eng) * C1 + (et2 - wsq) * C2;
            float ent = __logf(esum[j]) - pts[j] / ptn;
            lsum += (double)ent;
            lcnt++;
        }
    }

    const unsigned mask = 0xffffffffu;
#pragma unroll
    for (int o = 16; o > 0; o >>= 1) {
        lsum += __shfl_down_sync(mask, lsum, o);
        lcnt += __shfl_down_sync(mask, lcnt, o);
    }

    __shared__ double ssum[TPB / 32];
    __shared__ unsigned int scnt[TPB / 32];
    __shared__ int s_last;
    int lane = threadIdx.x & 31;
    int warp = threadIdx.x >> 5;
    if (lane == 0) { ssum[warp] = lsum; scnt[warp] = lcnt; }
    __syncthreads();

    if (warp == 0) {
        lsum = (lane < TPB / 32) ? ssum[lane] : 0.0;
        lcnt = (lane < TPB / 32) ? scnt[lane] : 0u;
#pragma unroll
        for (int o = 2; o > 0; o >>= 1) {
            lsum += __shfl_down_sync(mask, lsum, o);
            lcnt += __shfl_down_sync(mask, lcnt, o);
        }
        if (lane == 0) {
            g_part[blockIdx.x] = lsum;
            g_pcnt[blockIdx.x] = lcnt;
            __threadfence();
            unsigned int ticket = atomicAdd(&g_ticket, 1u);
            s_last = (ticket == NBLOCKS - 1);
        }
    }
    __syncthreads();

    // Last block reduces all partials and writes the scalar (fused finalize).
    if (s_last) {
        int tid = threadIdx.x;
        double s = 0.0;
        unsigned int c = 0u;
#pragma unroll 4
        for (int i = tid; i < NBLOCKS; i += TPB) {
            s += __ldcg(&g_part[i]);
            c += __ldcg(&g_pcnt[i]);
        }
#pragma unroll
        for (int o = 16; o > 0; o >>= 1) {
            s += __shfl_down_sync(mask, s, o);
            c += __shfl_down_sync(mask, c, o);
        }
        __syncthreads();
        if (lane == 0) { ssum[warp] = s; scnt[warp] = c; }
        __syncthreads();
        if (warp == 0) {
            s = (lane < TPB / 32) ? ssum[lane] : 0.0;
            c = (lane < TPB / 32) ? scnt[lane] : 0u;
#pragma unroll
            for (int o = 2; o > 0; o >>= 1) {
                s += __shfl_down_sync(mask, s, o);
                c += __shfl_down_sync(mask, c, o);
            }
            if (lane == 0) {
                out[0] = (float)(s / (double)c);
                g_ticket = 0u;
                __threadfence();
            }
        }
    }
}

extern "C" void kernel_launch(void* const* d_in, const int* in_sizes, int n_in,
                              void* d_out, int out_size) {
    const float* sim = (const float*)d_in[0];
    const float* gt  = (const float*)d_in[1];
    float* out = (float*)d_out;

    sce_main<<<NBLOCKS, TPB>>>(sim, gt, out);
}

// round 6
// speedup vs baseline: 1.0720x; 1.0720x over previous
#include <cuda_runtime.h>
#include <cstdint>

#define DD 64
#define H_ 256
#define W_ 512
#define HW_ (H_ * W_)
#define B_ 8
#define NPIX (B_ * HW_)
#define VEC 4
#define TPB 128
#define NTHREADS (NPIX / VEC)          // 262144
#define NBLOCKS (NTHREADS / TPB)       // 2048
#define STAGES 8

__device__ double g_part[NBLOCKS];
__device__ unsigned int g_pcnt[NBLOCKS];
__device__ unsigned int g_ticket;      // zero-init at load; last block resets each launch

__device__ __forceinline__ void cp16(uint32_t smem_addr, const void* gptr) {
    asm volatile("cp.async.cg.shared.global [%0], [%1], 16;\n"
                 :: "r"(smem_addr), "l"(gptr));
}
__device__ __forceinline__ void cp_commit() {
    asm volatile("cp.async.commit_group;\n" ::: "memory");
}
template <int N>
__device__ __forceinline__ void cp_wait() {
    asm volatile("cp.async.wait_group %0;\n" :: "n"(N) : "memory");
}

__global__ __launch_bounds__(TPB, 10) void sce_main(const float* __restrict__ sim,
                                                    const float* __restrict__ gt,
                                                    float* __restrict__ out) {
    __shared__ float4 ring[STAGES][TPB];   // 16 KB

    int tid = threadIdx.x;
    int t = blockIdx.x * TPB + tid;
    long long base = (long long)t * VEC;
    int b = (int)(base / HW_);
    int hw = (int)(base - (long long)b * HW_);

    float4 g4 = *reinterpret_cast<const float4*>(gt + base);
    float gts[VEC] = {g4.x, g4.y, g4.z, g4.w};

    const float E1  = 2.718281828459045f;
    const float IE1 = 0.3678794411714423f;
    const float C1  = 0.15651764274966565f;  // 1/(e^2-1)
    const float C2  = 1.1565176427496657f;   // 1/(1-e^-2)

    float u[VEC], v[VEC], esum[VEC], pts[VEC];
#pragma unroll
    for (int j = 0; j < VEC; ++j) {
        float hg = 0.5f * gts[j];
        u[j] = __expf(-hg);
        v[j] = __expf(hg);
        esum[j] = 0.f; pts[j] = 0.f;
    }

    const char* gp = reinterpret_cast<const char*>(sim + (long long)b * DD * HW_ + hw);
    const long long PB = (long long)HW_ * 4;   // plane stride in bytes
    uint32_t sm0 = (uint32_t)__cvta_generic_to_shared(&ring[0][tid]);
    const uint32_t SS = TPB * 16;               // stage stride in smem bytes

    // Prologue: stages 0..6 in flight (one group each).
#pragma unroll
    for (int s = 0; s < STAGES - 1; ++s) {
        cp16(sm0 + s * SS, gp + (long long)s * PB);
        cp_commit();
    }

    auto body = [&](float4 s4) {
        float sv[VEC] = {s4.x, s4.y, s4.z, s4.w};
#pragma unroll
        for (int j = 0; j < VEC; ++j) {
            float s = sv[j];
            esum[j] += __expf(s);
            float mm = fminf(u[j], v[j]);
            pts[j] = fmaf(mm * mm, s, pts[j]);
            u[j] *= E1;
            v[j] *= IE1;
        }
    };

    // Steady state: wait oldest, refill slot (holds plane d-1, already consumed), compute.
#pragma unroll 1
    for (int db = 0; db < DD - STAGES; db += STAGES) {
#pragma unroll
        for (int k = 0; k < STAGES; ++k) {
            int d = db + k;
            cp_wait<STAGES - 2>();                 // plane d resident
            cp16(sm0 + ((d + STAGES - 1) & (STAGES - 1)) * SS,
                 gp + (long long)(d + STAGES - 1) * PB);
            cp_commit();
            body(ring[d & (STAGES - 1)][tid]);
        }
    }
    // Drain: last 8 planes (56..63); planes 56..62 in flight, 63 issued at d=56 above? No:
    // at db loop end, issued up to plane (DD-STAGES-1)+STAGES-1 = DD-2. Issue plane 63 now.
    cp16(sm0 + ((DD - 1) & (STAGES - 1)) * SS, gp + (long long)(DD - 1) * PB);
    cp_commit();
#pragma unroll
    for (int k = 0; k < STAGES; ++k) {
        int d = DD - STAGES + k;
        cp_wait<STAGES - 2>();
        cp_commit();                               // empty group keeps count aligned
        body(ring[d & (STAGES - 1)][tid]);
    }
    cp_wait<0>();

    double lsum = 0.0;
    unsigned int lcnt = 0u;
#pragma unroll
    for (int j = 0; j < VEC; ++j) {
        if (isfinite(gts[j])) {
            // ptn closed form: t = gt-2*floor(gt/2); two geometric series
            float gtv = gts[j];
            float m0 = floorf(gtv * 0.5f);
            float tt = fmaf(-2.0f, m0, gtv);
            float et2 = __expf(tt - 2.0f);
            float e2t = 1.0f / et2;
            float eng = __expf(-gtv);
            float wsq = __expf(gtv - 128.0f);
            float ptn = (e2t - eng) * C1 + (et2 - wsq) * C2;
            float ent = __logf(esum[j]) - pts[j] / ptn;
            lsum += (double)ent;
            lcnt++;
        }
    }

    const unsigned mask = 0xffffffffu;
#pragma unroll
    for (int o = 16; o > 0; o >>= 1) {
        lsum += __shfl_down_sync(mask, lsum, o);
        lcnt += __shfl_down_sync(mask, lcnt, o);
    }

    __shared__ double ssum[TPB / 32];
    __shared__ unsigned int scnt[TPB / 32];
    __shared__ int s_last;
    int lane = tid & 31;
    int warp = tid >> 5;
    if (lane == 0) { ssum[warp] = lsum; scnt[warp] = lcnt; }
    __syncthreads();

    if (warp == 0) {
        lsum = (lane < TPB / 32) ? ssum[lane] : 0.0;
        lcnt = (lane < TPB / 32) ? scnt[lane] : 0u;
#pragma unroll
        for (int o = 2; o > 0; o >>= 1) {
            lsum += __shfl_down_sync(mask, lsum, o);
            lcnt += __shfl_down_sync(mask, lcnt, o);
        }
        if (lane == 0) {
            g_part[blockIdx.x] = lsum;
            g_pcnt[blockIdx.x] = lcnt;
            __threadfence();
            unsigned int ticket = atomicAdd(&g_ticket, 1u);
            s_last = (ticket == NBLOCKS - 1);
        }
    }
    __syncthreads();

    if (s_last) {
        double s = 0.0;
        unsigned int c = 0u;
#pragma unroll 4
        for (int i = tid; i < NBLOCKS; i += TPB) {
            s += __ldcg(&g_part[i]);
            c += __ldcg(&g_pcnt[i]);
        }
#pragma unroll
        for (int o = 16; o > 0; o >>= 1) {
            s += __shfl_down_sync(mask, s, o);
            c += __shfl_down_sync(mask, c, o);
        }
        __syncthreads();
        if (lane == 0) { ssum[warp] = s; scnt[warp] = c; }
        __syncthreads();
        if (warp == 0) {
            s = (lane < TPB / 32) ? ssum[lane] : 0.0;
            c = (lane < TPB / 32) ? scnt[lane] : 0u;
#pragma unroll
            for (int o = 2; o > 0; o >>= 1) {
                s += __shfl_down_sync(mask, s, o);
                c += __shfl_down_sync(mask, c, o);
            }
            if (lane == 0) {
                out[0] = (float)(s / (double)c);
                g_ticket = 0u;
                __threadfence();
            }
        }
    }
}

extern "C" void kernel_launch(void* const* d_in, const int* in_sizes, int n_in,
                              void* d_out, int out_size) {
    const float* sim = (const float*)d_in[0];
    const float* gt  = (const float*)d_in[1];
    float* out = (float*)d_out;

    sce_main<<<NBLOCKS, TPB>>>(sim, gt, out);
}